// round 1
// baseline (speedup 1.0000x reference)
#include <cuda_runtime.h>
#include <cuda_bf16.h>

// 4096 possible 12-bit rows -> 32 floats each = 512 KB LUT in device global.
__device__ float g_lut[4096 * 32];

// Build the LUT: replicate the reference math for every possible 12-bit input.
// pat:  (4, 3, 4096) f32   pattern_tables
// pos:  (4, 5, 4096) f32   position_tables
// conn: (4, 5, 12)   i32   position_conn
__global__ void build_lut_kernel(const float* __restrict__ pat,
                                 const float* __restrict__ pos,
                                 const int*   __restrict__ conn)
{
    int b = blockIdx.x * blockDim.x + threadIdx.x;
    if (b >= 4096) return;

    float out[32];
#pragma unroll
    for (int s = 0; s < 4; s++) {
        const int n      = s + 1;
        const int bits3n = 3 * n;
        const int paddr  = b & ((1 << bits3n) - 1);   // last 3n columns, MSB-first

        // pattern bits
        int pb = 0;
#pragma unroll
        for (int j = 0; j < 3; j++) {
            float v  = pat[(s * 3 + j) * 4096 + paddr];
            int bit  = (v > 0.5f) ? 1 : 0;
            out[s * 8 + j] = (float)bit;
            pb |= bit << j;
        }

        // pos_in bit i (i < 3n)  = ctx[i] = bit (3n-1-i) of paddr
        // pos_in bit (3n + j)    = pbit j
        const int in_bits = bits3n + 3;
        const int nb      = (in_bits < 12) ? in_bits : 12;
#pragma unroll
        for (int k = 0; k < 5; k++) {
            int addr = 0;
            for (int j = 0; j < nb; j++) {
                int c = conn[(s * 5 + k) * 12 + j] % in_bits;
                int bit = (c < bits3n) ? ((paddr >> (bits3n - 1 - c)) & 1)
                                       : ((pb >> (c - bits3n)) & 1);
                addr |= bit << j;
            }
            out[s * 8 + 3 + k] = pos[(s * 5 + k) * 4096 + addr];
        }
    }

    float4*       dst = (float4*)&g_lut[b * 32];
    const float4* src = (const float4*)out;
#pragma unroll
    for (int i = 0; i < 8; i++) dst[i] = src[i];
}

// Main kernel: pure gather. 1 thread = 1 row.
// Read 48 B of type_bits (streaming), pack 12 bits, copy 128 B from LUT (L2-hot)
// to the output row (streaming store).
__global__ void gather_kernel(const int* __restrict__ tb,
                              float* __restrict__ out,
                              int nrows)
{
    int row = blockIdx.x * blockDim.x + threadIdx.x;
    if (row >= nrows) return;

    const int4* t4 = (const int4*)(tb + (size_t)row * 12);
    int4 a = __ldcs(t4 + 0);
    int4 c = __ldcs(t4 + 1);
    int4 d = __ldcs(t4 + 2);

    // column c gets weight 2^(11-c)  (MSB-first packing)
    int b = (a.x << 11) | (a.y << 10) | (a.z << 9) | (a.w << 8)
          | (c.x << 7)  | (c.y << 6)  | (c.z << 5) | (c.w << 4)
          | (d.x << 3)  | (d.y << 2)  | (d.z << 1) |  d.w;

    const float4* lut = (const float4*)&g_lut[b * 32];
    float4*       o   = (float4*)(out + (size_t)row * 32);

    float4 v0 = __ldg(&lut[0]);
    float4 v1 = __ldg(&lut[1]);
    float4 v2 = __ldg(&lut[2]);
    float4 v3 = __ldg(&lut[3]);
    float4 v4 = __ldg(&lut[4]);
    float4 v5 = __ldg(&lut[5]);
    float4 v6 = __ldg(&lut[6]);
    float4 v7 = __ldg(&lut[7]);

    __stcs(&o[0], v0);
    __stcs(&o[1], v1);
    __stcs(&o[2], v2);
    __stcs(&o[3], v3);
    __stcs(&o[4], v4);
    __stcs(&o[5], v5);
    __stcs(&o[6], v6);
    __stcs(&o[7], v7);
}

extern "C" void kernel_launch(void* const* d_in, const int* in_sizes, int n_in,
                              void* d_out, int out_size)
{
    const int*   tb   = (const int*)  d_in[0];  // type_bits      (B, 12) i32
    const float* pat  = (const float*)d_in[1];  // pattern_tables (4,3,4096) f32
    const float* pos  = (const float*)d_in[2];  // position_tables(4,5,4096) f32
    const int*   conn = (const int*)  d_in[3];  // position_conn  (4,5,12) i32
    float*       out  = (float*)d_out;          // (B, 4, 8) f32

    int nrows = in_sizes[0] / 12;

    build_lut_kernel<<<32, 128>>>(pat, pos, conn);
    gather_kernel<<<(nrows + 255) / 256, 256>>>(tb, out, nrows);
}

// round 2
// speedup vs baseline: 2.0709x; 2.0709x over previous
#include <cuda_runtime.h>
#include <cuda_bf16.h>

// 4096 possible 12-bit rows -> 32 floats each = 512 KB LUT in device global.
__device__ float g_lut[4096 * 32];

// Build the LUT: replicate the reference math for every possible 12-bit input.
__global__ void build_lut_kernel(const float* __restrict__ pat,
                                 const float* __restrict__ pos,
                                 const int*   __restrict__ conn)
{
    int b = blockIdx.x * blockDim.x + threadIdx.x;
    if (b >= 4096) return;

    float out[32];
#pragma unroll
    for (int s = 0; s < 4; s++) {
        const int n      = s + 1;
        const int bits3n = 3 * n;
        const int paddr  = b & ((1 << bits3n) - 1);   // last 3n columns, MSB-first

        int pb = 0;
#pragma unroll
        for (int j = 0; j < 3; j++) {
            float v  = pat[(s * 3 + j) * 4096 + paddr];
            int bit  = (v > 0.5f) ? 1 : 0;
            out[s * 8 + j] = (float)bit;
            pb |= bit << j;
        }

        const int in_bits = bits3n + 3;
        const int nb      = (in_bits < 12) ? in_bits : 12;
#pragma unroll
        for (int k = 0; k < 5; k++) {
            int addr = 0;
            for (int j = 0; j < nb; j++) {
                int c = conn[(s * 5 + k) * 12 + j] % in_bits;
                int bit = (c < bits3n) ? ((paddr >> (bits3n - 1 - c)) & 1)
                                       : ((pb >> (c - bits3n)) & 1);
                addr |= bit << j;
            }
            out[s * 8 + 3 + k] = pos[(s * 5 + k) * 4096 + addr];
        }
    }

    float4*       dst = (float4*)&g_lut[b * 32];
    const float4* src = (const float4*)out;
#pragma unroll
    for (int i = 0; i < 8; i++) dst[i] = src[i];
}

// Main kernel: block of 256 threads handles 64 rows.
//   Stage 1: coalesced load of 64 rows * 12 ints into smem (as int4).
//   Stage 2: 64 threads pack one 12-bit index each.
//   Stage 3: 512 (row, float4-chunk) tasks, 2 per thread: coalesced LUT gather
//            (8 lanes share one 128B line) + fully coalesced streaming store.
#define ROWS_PER_BLOCK 64
#define THREADS 256

__global__ __launch_bounds__(THREADS)
void gather_kernel(const int* __restrict__ tb,
                   float* __restrict__ out,
                   int nrows)
{
    __shared__ int s_bits[ROWS_PER_BLOCK * 12];   // 3072 B
    __shared__ int s_idx[ROWS_PER_BLOCK];

    const int tid      = threadIdx.x;
    const int row_base = blockIdx.x * ROWS_PER_BLOCK;
    const int rows     = min(ROWS_PER_BLOCK, nrows - row_base);
    if (rows <= 0) return;

    // Stage 1: coalesced int4 load of rows*12 ints.
    {
        const int n_int4 = (rows * 12) / 4;   // rows*12 always divisible by 4
        const int4* src  = (const int4*)(tb + (size_t)row_base * 12);
        int4* dst        = (int4*)s_bits;
        for (int i = tid; i < n_int4; i += THREADS)
            dst[i] = __ldcs(src + i);
    }
    __syncthreads();

    // Stage 2: pack 12 bits MSB-first per row.
    if (tid < rows) {
        const int* r = &s_bits[tid * 12];
        int b = 0;
#pragma unroll
        for (int c = 0; c < 12; c++)
            b |= r[c] << (11 - c);
        s_idx[tid] = b;
    }
    __syncthreads();

    // Stage 3: 8 float4 chunks per row, coalesced.
    float4* out4 = (float4*)out + (size_t)row_base * 8;
    const int ntasks = rows * 8;
#pragma unroll
    for (int t = tid; t < ntasks; t += THREADS) {
        const int row   = t >> 3;
        const int chunk = t & 7;
        const float4* lut = (const float4*)&g_lut[s_idx[row] * 32];
        float4 v = __ldg(&lut[chunk]);
        __stcs(&out4[t], v);
    }
}

extern "C" void kernel_launch(void* const* d_in, const int* in_sizes, int n_in,
                              void* d_out, int out_size)
{
    const int*   tb   = (const int*)  d_in[0];  // type_bits      (B, 12) i32
    const float* pat  = (const float*)d_in[1];  // pattern_tables (4,3,4096) f32
    const float* pos  = (const float*)d_in[2];  // position_tables(4,5,4096) f32
    const int*   conn = (const int*)  d_in[3];  // position_conn  (4,5,12) i32
    float*       out  = (float*)d_out;          // (B, 4, 8) f32

    int nrows = in_sizes[0] / 12;

    build_lut_kernel<<<32, 128>>>(pat, pos, conn);

    int nblocks = (nrows + ROWS_PER_BLOCK - 1) / ROWS_PER_BLOCK;
    gather_kernel<<<nblocks, THREADS>>>(tb, out, nrows);
}

// round 3
// speedup vs baseline: 2.2402x; 1.0817x over previous
#include <cuda_runtime.h>
#include <cuda_bf16.h>

// 4096 possible 12-bit rows -> 32 floats each = 512 KB LUT in device global.
__device__ float g_lut[4096 * 32];

// Build the LUT, parallelized over (b, s): 4096 * 4 = 16384 threads.
// Each thread computes the 8 floats for scale s of input pattern b.
__global__ void build_lut_kernel(const float* __restrict__ pat,
                                 const float* __restrict__ pos,
                                 const int*   __restrict__ conn)
{
    int idx = blockIdx.x * blockDim.x + threadIdx.x;
    if (idx >= 4096 * 4) return;
    const int b = idx >> 2;
    const int s = idx & 3;

    const int bits3n = 3 * (s + 1);
    const int paddr  = b & ((1 << bits3n) - 1);   // last 3n columns, MSB-first

    float out[8];
    int pb = 0;
#pragma unroll
    for (int j = 0; j < 3; j++) {
        float v = pat[(s * 3 + j) * 4096 + paddr];
        int bit = (v > 0.5f) ? 1 : 0;
        out[j]  = (float)bit;
        pb |= bit << j;
    }

    const int in_bits = bits3n + 3;
    const int nb      = (in_bits < 12) ? in_bits : 12;
#pragma unroll
    for (int k = 0; k < 5; k++) {
        int addr = 0;
        for (int j = 0; j < nb; j++) {
            int c   = conn[(s * 5 + k) * 12 + j] % in_bits;
            int bit = (c < bits3n) ? ((paddr >> (bits3n - 1 - c)) & 1)
                                   : ((pb >> (c - bits3n)) & 1);
            addr |= bit << j;
        }
        out[3 + k] = pos[(s * 5 + k) * 4096 + addr];
    }

    float4* dst = (float4*)&g_lut[b * 32 + s * 8];
    dst[0] = ((const float4*)out)[0];
    dst[1] = ((const float4*)out)[1];
}

// Main kernel: block of 256 threads handles 128 rows.
//   Stage 1: coalesced int4 load of 128 rows * 12 ints into smem.
//   Stage 2: 128 threads pack one 12-bit index each.
//   Stage 3: 1024 (row, float4-chunk) tasks, 4 per thread. All 4 LUT loads
//            issued before any store (MLP=4), stores fully coalesced streaming.
#define ROWS_PER_BLOCK 128
#define THREADS 256

__global__ __launch_bounds__(THREADS)
void gather_kernel(const int* __restrict__ tb,
                   float* __restrict__ out,
                   int nrows)
{
    __shared__ int s_bits[ROWS_PER_BLOCK * 12];   // 6144 B
    __shared__ int s_idx[ROWS_PER_BLOCK];

    const int tid      = threadIdx.x;
    const int row_base = blockIdx.x * ROWS_PER_BLOCK;
    const int rows     = min(ROWS_PER_BLOCK, nrows - row_base);
    if (rows <= 0) return;

    // Stage 1: coalesced int4 loads (rows*12 divisible by 4).
    {
        const int n_int4 = (rows * 12) >> 2;              // 384 for full block
        const int4* src  = (const int4*)(tb + (size_t)row_base * 12);
        int4* dst        = (int4*)s_bits;
        for (int i = tid; i < n_int4; i += THREADS)
            dst[i] = __ldcs(src + i);
    }
    __syncthreads();

    // Stage 2: pack 12 bits MSB-first per row.
    if (tid < rows) {
        const int* r = &s_bits[tid * 12];
        int b = 0;
#pragma unroll
        for (int c = 0; c < 12; c++)
            b |= r[c] << (11 - c);
        s_idx[tid] = b;
    }
    __syncthreads();

    float4* out4 = (float4*)out + (size_t)row_base * 8;

    if (rows == ROWS_PER_BLOCK) {
        // Fast path: batch 4 independent LUT loads, then 4 coalesced stores.
        float4 v[4];
#pragma unroll
        for (int j = 0; j < 4; j++) {
            const int t     = tid + j * THREADS;
            const int row   = t >> 3;
            const int chunk = t & 7;
            v[j] = __ldg((const float4*)&g_lut[s_idx[row] * 32] + chunk);
        }
#pragma unroll
        for (int j = 0; j < 4; j++)
            __stcs(&out4[tid + j * THREADS], v[j]);
    } else {
        const int ntasks = rows * 8;
        for (int t = tid; t < ntasks; t += THREADS) {
            const int row   = t >> 3;
            const int chunk = t & 7;
            float4 v = __ldg((const float4*)&g_lut[s_idx[row] * 32] + chunk);
            __stcs(&out4[t], v);
        }
    }
}

extern "C" void kernel_launch(void* const* d_in, const int* in_sizes, int n_in,
                              void* d_out, int out_size)
{
    const int*   tb   = (const int*)  d_in[0];  // type_bits      (B, 12) i32
    const float* pat  = (const float*)d_in[1];  // pattern_tables (4,3,4096) f32
    const float* pos  = (const float*)d_in[2];  // position_tables(4,5,4096) f32
    const int*   conn = (const int*)  d_in[3];  // position_conn  (4,5,12) i32
    float*       out  = (float*)d_out;          // (B, 4, 8) f32

    int nrows = in_sizes[0] / 12;

    build_lut_kernel<<<64, 256>>>(pat, pos, conn);

    int nblocks = (nrows + ROWS_PER_BLOCK - 1) / ROWS_PER_BLOCK;
    gather_kernel<<<nblocks, THREADS>>>(tb, out, nrows);
}